// round 11
// baseline (speedup 1.0000x reference)
#include <cuda_runtime.h>
#include <cuda_bf16.h>
#include <cstdint>

// Output: [32, 4096, 1024] fp32. out[..., c] = coef if (c odd && c < 1022) else 0.
// Row = 1024 floats = 128 chunks of 8 floats (32B). Every chunk is
// (0,coef,0,coef,0,coef,0,coef) except the last chunk of each row, which is
// (0,coef,0,coef,0,coef,0,0) (col 1023 is odd but >= chns-2, never written).
//
// sm_100a 256-bit stores (st.global.v8.f32 = STG.E.256): halves store-instr
// and L1TEX wavefront count per byte vs float4. Granularity kept at the
// round-9 winner (32KB per block): 16384 blocks x 256 threads x 4 chunks.
// Block base is a multiple of 256 chunks and per-iteration stride is 256
// chunks, so chunk_in_row == (tid & 127) for every store: only lanes with
// tid&127==127 ever write a row-tail chunk -> store value is a per-thread
// constant, zero per-iteration logic.

static constexpr long long TOTAL_CHUNKS      = 32LL * 4096LL * 1024LL / 8; // 16,777,216
static constexpr int       THREADS           = 256;
static constexpr int       CHUNKS_PER_THREAD = 4;
static constexpr int       CHUNKS_PER_BLOCK  = THREADS * CHUNKS_PER_THREAD; // 1024
static constexpr int       BLOCKS            = (int)(TOTAL_CHUNKS / CHUNKS_PER_BLOCK); // 16384

__global__ __launch_bounds__(THREADS)
void posenc_fill_kernel(float* __restrict__ out,
                        const float* __restrict__ coef_ptr) {
    const float coef = __ldg(coef_ptr);
    // lanes at tid&127==127 own the last 32B chunk of a row: float 7 (col 1023) = 0
    const float w7 = ((threadIdx.x & 127) == 127) ? 0.0f : coef;
    const float z = 0.0f;

    float* p = out + ((long long)blockIdx.x * CHUNKS_PER_BLOCK + threadIdx.x) * 8;
#pragma unroll
    for (int k = 0; k < CHUNKS_PER_THREAD; ++k) {
        float* q = p + (long long)k * THREADS * 8;   // stride 8KB
        asm volatile(
            "st.global.v8.f32 [%0], {%1, %2, %3, %4, %5, %6, %7, %8};"
            :: "l"(q),
               "f"(z), "f"(coef), "f"(z), "f"(coef),
               "f"(z), "f"(coef), "f"(z), "f"(w7)
            : "memory");
    }
}

extern "C" void kernel_launch(void* const* d_in, const int* in_sizes, int n_in,
                              void* d_out, int out_size) {
    const float* coef = (const float*)d_in[n_in - 1];  // coef_param is last input
    posenc_fill_kernel<<<BLOCKS, THREADS>>>((float*)d_out, coef);
}

// round 12
// speedup vs baseline: 1.0106x; 1.0106x over previous
#include <cuda_runtime.h>
#include <cuda_bf16.h>
#include <cstdint>

// Output: [32, 4096, 1024] fp32. out[..., c] = coef if (c odd && c < 1022) else 0.
// Row = 1024 floats = 256 float4s; all float4s are (0,coef,0,coef) except the
// last float4 of each row which is (0,coef,0,0).
//
// Final policy probe: round-10 config (32768 blocks x 256 threads x 4 float4
// stores, best wall 75.8us / ncu 74.0us, DRAM 79%) with __stwt (st.global.wt,
// write-through) instead of default stores. Tests whether L2 dirty-line
// writeback scheduling is shaving the last ~20% off the DRAM write stream.
// Exhausted already: store width (128/256b), evict-first, granularity
// (1024..131072 blocks), occupancy. All plateau at ~6.46 TB/s.
// VEC_PER_BLOCK = 1024, a multiple of 256, so every store by thread t lands
// at within-row float4 index t: only tid==255 writes row-tail float4s and
// the store value is a per-thread constant.

static constexpr long long TOTAL_VEC4     = 32LL * 4096LL * 1024LL / 4;  // 33,554,432
static constexpr int       THREADS        = 256;
static constexpr int       VEC_PER_THREAD = 4;
static constexpr int       VEC_PER_BLOCK  = THREADS * VEC_PER_THREAD;    // 1024
static constexpr int       BLOCKS         = (int)(TOTAL_VEC4 / VEC_PER_BLOCK); // 32768

__global__ __launch_bounds__(THREADS)
void posenc_fill_kernel(float4* __restrict__ out,
                        const float* __restrict__ coef_ptr) {
    const float coef = __ldg(coef_ptr);
    const float w3 = (threadIdx.x == THREADS - 1) ? 0.0f : coef;
    const float4 val = make_float4(0.0f, coef, 0.0f, w3);

    float4* p = out + (long long)blockIdx.x * VEC_PER_BLOCK + threadIdx.x;
#pragma unroll
    for (int k = 0; k < VEC_PER_THREAD; ++k) {
        __stwt(p + k * THREADS, val);   // STG.E.128.WT — write-through to DRAM
    }
}

extern "C" void kernel_launch(void* const* d_in, const int* in_sizes, int n_in,
                              void* d_out, int out_size) {
    const float* coef = (const float*)d_in[n_in - 1];  // coef_param is last input
    posenc_fill_kernel<<<BLOCKS, THREADS>>>((float4*)d_out, coef);
}